// round 16
// baseline (speedup 1.0000x reference)
#include <cuda_runtime.h>

// CRF forward loss: B=1024, T=512, K=32.
// inputs: emissions f32 [B,T,K], tags i32 [B,T], mask int32 [B,T], trans f32 [K,K]
// output: scalar f32 loss = mean_b( log_z - em_score - tr_score )
//
// R16: TWO independent scalar linear-space chains per warp (batches 2w,2w+1),
//   one warp per SMSP (128 blocks x 128 threads). The chains share the E
//   registers and ONE __syncwarp per step-pair; their FFMA trees interleave
//   in the issue stream, hiding each other's latency (in-warp ILP instead of
//   a second warp). Per-chain math identical to the passing R15:
//   p_j = 2^(alpha_j - off); step: sync; 8x LDS.128; 32 FFMA (4 accs);
//   pn = s * r_t (r from MUFU prefetch ring); sel by mask bit; STS.
//   Renorm every 4 steps via rcp(p0) with p0 = x0.x from the dot's own LDS;
//   cacc -= lg2(rb). Tags/mask 2 chunks ahead, emtag gather 1 chunk ahead.
//   Scores warp-reduced; fused mean via atomicInc-wrap.

#define FULLM 0xffffffffu

constexpr int Bc  = 1024;
constexpr int Tc  = 512;
constexpr int Kc  = 32;
constexpr int WPB = 4;                       // warps per block
constexpr int NBLK = Bc / (WPB * 2);         // 128 blocks, 2 batches/warp

__device__ float    g_partial[Bc];
__device__ unsigned g_ctr = 0;               // wraps to 0 each launch -> replay-safe

__device__ __forceinline__ float ex2f_(float x) {
    float r; asm("ex2.approx.f32 %0, %1;" : "=f"(r) : "f"(x)); return r;
}
__device__ __forceinline__ float lg2f_(float x) {
    float r; asm("lg2.approx.f32 %0, %1;" : "=f"(r) : "f"(x)); return r;
}
__device__ __forceinline__ float rcpf_(float x) {
    float r; asm("rcp.approx.f32 %0, %1;" : "=f"(r) : "f"(x)); return r;
}

// 32-term dot of broadcast smem vector pv[] with per-lane column E[],
// 4 accumulators. Returns s; x00 = pv[0].x (for renorm tracking).
#define DOT32(pv, E, sOut, x00Out)                                        \
    do {                                                                  \
        float4 x0 = (pv)[0], x1 = (pv)[1], x2 = (pv)[2], x3 = (pv)[3];    \
        float4 x4 = (pv)[4], x5 = (pv)[5], x6 = (pv)[6], x7 = (pv)[7];    \
        float s0 = x0.x * (E)[0];                                         \
        float s1 = x0.y * (E)[1];                                         \
        float s2 = x0.z * (E)[2];                                         \
        float s3 = x0.w * (E)[3];                                         \
        s0 = fmaf(x1.x, (E)[4],  s0); s1 = fmaf(x1.y, (E)[5],  s1);       \
        s2 = fmaf(x1.z, (E)[6],  s2); s3 = fmaf(x1.w, (E)[7],  s3);       \
        s0 = fmaf(x2.x, (E)[8],  s0); s1 = fmaf(x2.y, (E)[9],  s1);       \
        s2 = fmaf(x2.z, (E)[10], s2); s3 = fmaf(x2.w, (E)[11], s3);       \
        s0 = fmaf(x3.x, (E)[12], s0); s1 = fmaf(x3.y, (E)[13], s1);       \
        s2 = fmaf(x3.z, (E)[14], s2); s3 = fmaf(x3.w, (E)[15], s3);       \
        s0 = fmaf(x4.x, (E)[16], s0); s1 = fmaf(x4.y, (E)[17], s1);       \
        s2 = fmaf(x4.z, (E)[18], s2); s3 = fmaf(x4.w, (E)[19], s3);       \
        s0 = fmaf(x5.x, (E)[20], s0); s1 = fmaf(x5.y, (E)[21], s1);       \
        s2 = fmaf(x5.z, (E)[22], s2); s3 = fmaf(x5.w, (E)[23], s3);       \
        s0 = fmaf(x6.x, (E)[24], s0); s1 = fmaf(x6.y, (E)[25], s1);       \
        s2 = fmaf(x6.z, (E)[26], s2); s3 = fmaf(x6.w, (E)[27], s3);       \
        s0 = fmaf(x7.x, (E)[28], s0); s1 = fmaf(x7.y, (E)[29], s1);       \
        s2 = fmaf(x7.z, (E)[30], s2); s3 = fmaf(x7.w, (E)[31], s3);       \
        (sOut)  = (s0 + s1) + (s2 + s3);                                  \
        (x00Out) = x0.x;                                                  \
    } while (0)

__global__ void __launch_bounds__(128, 1)
crf_forward(const float* __restrict__ em,
            const int* __restrict__ tags,
            const int* __restrict__ mask,
            const float* __restrict__ trans,
            float* __restrict__ out)
{
    __shared__ float tr_s[Kc * Kc];
    __shared__ __align__(16) float pbA[WPB][2][Kc];   // chain A double buffer
    __shared__ __align__(16) float pbB[WPB][2][Kc];   // chain B double buffer
    __shared__ float red[WPB];
    __shared__ int   sdone;

    const int lane = threadIdx.x & 31;
    const int wid  = threadIdx.x >> 5;

    for (int i = threadIdx.x; i < Kc * Kc; i += 128)
        tr_s[i] = trans[i];
    __syncthreads();

    const float L2E = 1.4426950408889634f;   // log2(e)
    const float LN2 = 0.6931471805599453f;

    // lane j holds column j of E = exp(transitions)  (shared by both chains)
    float E[Kc];
#pragma unroll
    for (int i = 0; i < Kc; i++)
        E[i] = __expf(tr_s[i * Kc + lane]);

    const int bA = (blockIdx.x * WPB + wid) * 2;
    const int bB = bA + 1;
    const float* emA = em   + (size_t)bA * Tc * Kc;
    const float* emBp = em  + (size_t)bB * Tc * Kc;
    const int*   tgA = tags + (size_t)bA * Tc;
    const int*   tgBp = tags + (size_t)bB * Tc;
    const int*   mA  = mask + (size_t)bA * Tc;
    const int*   mBp = mask + (size_t)bB * Tc;

    // ---- init both chains: alpha0 = em[0] ----
    float e0A = emA[lane],  e0B = emBp[lane];
    float r0A = __shfl_sync(FULLM, e0A, 0);
    float r0B = __shfl_sync(FULLM, e0B, 0);
    float cA  = r0A * L2E,  cB = r0B * L2E;
    float pA  = ex2f_((e0A - r0A) * L2E);    // pA[0] == 1
    float pB  = ex2f_((e0B - r0B) * L2E);
    pbA[wid][0][lane] = pA;
    pbB[wid][0][lane] = pB;
    float p0A = 1.0f, p0B = 1.0f;            // tracked p[0] per chain

    // prefetch rings: r_t = 2^(em*L2E) for rows t..t+3
    float nA0 = ex2f_(emA[0 * Kc + lane] * L2E);
    float nA1 = ex2f_(emA[1 * Kc + lane] * L2E);
    float nA2 = ex2f_(emA[2 * Kc + lane] * L2E);
    float nA3 = ex2f_(emA[3 * Kc + lane] * L2E);
    float nB0 = ex2f_(emBp[0 * Kc + lane] * L2E);
    float nB1 = ex2f_(emBp[1 * Kc + lane] * L2E);
    float nB2 = ex2f_(emBp[2 * Kc + lane] * L2E);
    float nB3 = ex2f_(emBp[3 * Kc + lane] * L2E);

    // chunk score pipeline (per chain): current + next prefetched
    int   tgcA = tgA[lane],       tgcB = tgBp[lane];
    int   mkcA = mA[lane],        mkcB = mBp[lane];
    float etcA = emA[(size_t)lane * Kc + tgcA];
    float etcB = emBp[(size_t)lane * Kc + tgcB];
    int   tgnA = tgA[32 + lane],  tgnB = tgBp[32 + lane];
    int   mknA = mA[32 + lane],   mknB = mBp[32 + lane];

    float esA = 0.f, tsA = 0.f, esB = 0.f, tsB = 0.f;
    int   cryA = 0, cryB = 0;

    for (int ch = 0; ch < Tc / 32; ch++) {
        // ---- consume chunk ch's prefetched tag/mask/emtag (both chains) ----
        unsigned mbitsA = __ballot_sync(FULLM, mkcA != 0);
        unsigned mbitsB = __ballot_sync(FULLM, mkcB != 0);
        int tpA = __shfl_up_sync(FULLM, tgcA, 1);
        int tpB = __shfl_up_sync(FULLM, tgcB, 1);
        if (lane == 0) { tpA = cryA; tpB = cryB; }
        cryA = __shfl_sync(FULLM, tgcA, 31);
        cryB = __shfl_sync(FULLM, tgcB, 31);
        const int t_l = ch * 32 + lane;
        if (mkcA) { esA += etcA; if (t_l > 0) tsA += tr_s[tpA * Kc + tgcA]; }
        if (mkcB) { esB += etcB; if (t_l > 0) tsB += tr_s[tpB * Kc + tgcB]; }

        int chn  = min(ch + 1, Tc / 32 - 1);
        int chnn = min(ch + 2, Tc / 32 - 1);
        float etnA = emA[(size_t)(chn * 32 + lane) * Kc + tgnA];
        float etnB = emBp[(size_t)(chn * 32 + lane) * Kc + tgnB];
        int tgnnA = tgA[chnn * 32 + lane];
        int tgnnB = tgBp[chnn * 32 + lane];
        int mknnA = mA[chnn * 32 + lane];
        int mknnB = mBp[chnn * 32 + lane];

        for (int jj = 0; jj < 32; jj += 4) {
            const int tb = ch * 32 + jj;

            // renorm factors (1-block-stale p[0], uniform across lanes)
            float rbA = rcpf_(p0A), lbA = lg2f_(rbA);
            float rbB = rcpf_(p0B), lbB = lg2f_(rbB);

            float rqA[4] = {nA0, nA1, nA2, nA3};
            float rqB[4] = {nB0, nB1, nB2, nB3};
            int t4 = min(tb + 4, Tc - 1);
            int t5 = min(tb + 5, Tc - 1);
            int t6 = min(tb + 6, Tc - 1);
            int t7 = min(tb + 7, Tc - 1);
            nA0 = ex2f_(emA[t4 * Kc + lane] * L2E);
            nA1 = ex2f_(emA[t5 * Kc + lane] * L2E);
            nA2 = ex2f_(emA[t6 * Kc + lane] * L2E);
            nA3 = ex2f_(emA[t7 * Kc + lane] * L2E);
            nB0 = ex2f_(emBp[t4 * Kc + lane] * L2E);
            nB1 = ex2f_(emBp[t5 * Kc + lane] * L2E);
            nB2 = ex2f_(emBp[t6 * Kc + lane] * L2E);
            nB3 = ex2f_(emBp[t7 * Kc + lane] * L2E);

#pragma unroll
            for (int q = 0; q < 4; q++) {
                const int t = tb + q;
                __syncwarp();                 // one sync covers BOTH chains
                if (t != 0) {
                    const float4* pvA = reinterpret_cast<const float4*>(
                        pbA[wid][(t + 1) & 1]);
                    const float4* pvB = reinterpret_cast<const float4*>(
                        pbB[wid][(t + 1) & 1]);

                    float sA, xA0, sB, xB0;
                    DOT32(pvA, E, sA, xA0);
                    DOT32(pvB, E, sB, xB0);

                    float pnA = sA * rqA[q];
                    float pnB = sB * rqB[q];
                    pA = ((mbitsA >> (jj + q)) & 1u) ? pnA : pA;
                    pB = ((mbitsB >> (jj + q)) & 1u) ? pnB : pB;
                    if (q == 0) {             // uniform renorm, post-select
                        pA *= rbA;  cA -= lbA;
                        pB *= rbB;  cB -= lbB;
                    }
                    p0A = (q == 0) ? xA0 * rbA : xA0;
                    p0B = (q == 0) ? xB0 * rbB : xB0;
                }
                pbA[wid][t & 1][lane] = pA;
                pbB[wid][t & 1][lane] = pB;
            }
        }

        tgcA = tgnA; mkcA = mknA; etcA = etnA; tgnA = tgnnA; mknA = mknnA;
        tgcB = tgnB; mkcB = mknB; etcB = etnB; tgnB = tgnnB; mknB = mknnB;
    }

    // ---- final: logz = (cacc + lg2(sum_j p_j)) * ln2, + score reduction ----
    float psA = pA, psB = pB;
    float scA = esA + tsA, scB = esB + tsB;
#pragma unroll
    for (int o = 16; o; o >>= 1) {
        psA += __shfl_xor_sync(FULLM, psA, o);
        psB += __shfl_xor_sync(FULLM, psB, o);
        scA += __shfl_xor_sync(FULLM, scA, o);
        scB += __shfl_xor_sync(FULLM, scB, o);
    }
    float logzA = (cA + lg2f_(psA)) * LN2;
    float logzB = (cB + lg2f_(psB)) * LN2;

    if (lane == 0) {
        __stcg(&g_partial[bA], logzA - scA);
        __stcg(&g_partial[bB], logzB - scB);
    }

    // ---- fused mean: last block to arrive reduces all partials ----
    __syncthreads();
    if (threadIdx.x == 0) {
        __threadfence();
        unsigned r = atomicInc(&g_ctr, (unsigned)gridDim.x - 1);
        sdone = (r == gridDim.x - 1) ? 1 : 0;
    }
    __syncthreads();
    if (sdone) {
        float s = 0.f;
        for (int i = threadIdx.x; i < Bc; i += 128)
            s += __ldcg(&g_partial[i]);
#pragma unroll
        for (int o = 16; o; o >>= 1)
            s += __shfl_xor_sync(FULLM, s, o);
        if (lane == 0) red[wid] = s;
        __syncthreads();
        if (threadIdx.x < 32) {
            float v = (threadIdx.x < WPB) ? red[threadIdx.x] : 0.f;
#pragma unroll
            for (int o = 2; o; o >>= 1)
                v += __shfl_xor_sync(FULLM, v, o);
            if (threadIdx.x == 0)
                out[0] = v * (1.0f / (float)Bc);
        }
    }
}

extern "C" void kernel_launch(void* const* d_in, const int* in_sizes, int n_in,
                              void* d_out, int out_size)
{
    const float* em    = (const float*)d_in[0];
    const int*   tags  = (const int*)d_in[1];
    const int*   mask  = (const int*)d_in[2];
    const float* trans = (const float*)d_in[3];
    float*       out   = (float*)d_out;

    crf_forward<<<NBLK, 128>>>(em, tags, mask, trans, out);
}

// round 17
// speedup vs baseline: 1.2661x; 1.2661x over previous
#include <cuda_runtime.h>

// CRF forward loss: B=1024, T=512, K=32.
// inputs: emissions f32 [B,T,K], tags i32 [B,T], mask int32 [B,T], trans f32 [K,K]
// output: scalar f32 loss = mean_b( log_z - em_score - tr_score )
//
// R17 = R15 skeleton (2 warps/SMSP, 1 batch/warp, linear-space chain, zero
// in-chain transcendentals) + PAIR-PACKED f32x2 dot within each batch:
//   E2[k] = (exp(tr[2k][j]), exp(tr[2k+1][j]))  (lane j = column j)
//   step: sync; 8x LDS.128 -> 16 pairs; 16x fma.rn.f32x2 into 4 packed accs
//   (chain depth 4); fold halves; pn = s * r_t (MUFU ring); sel; STS.
//   Renorm every 4 steps via rcp(p0), p0 = lo half of the first pair (free).
//   Tags/mask 2 chunks ahead, emtag gather 1 chunk ahead; scores warp-reduced;
//   fused mean via atomicInc-wrap. (R16 lesson: never <2 warps/SMSP.)

#define FULLM 0xffffffffu
typedef unsigned long long ull;

constexpr int Bc  = 1024;
constexpr int Tc  = 512;
constexpr int Kc  = 32;
constexpr int WPB = 8;                       // warps per block
constexpr int NBLK = Bc / WPB;               // 128 blocks, 1 batch/warp

__device__ float    g_partial[Bc];
__device__ unsigned g_ctr = 0;               // wraps to 0 each launch -> replay-safe

__device__ __forceinline__ float ex2f_(float x) {
    float r; asm("ex2.approx.f32 %0, %1;" : "=f"(r) : "f"(x)); return r;
}
__device__ __forceinline__ float lg2f_(float x) {
    float r; asm("lg2.approx.f32 %0, %1;" : "=f"(r) : "f"(x)); return r;
}
__device__ __forceinline__ float rcpf_(float x) {
    float r; asm("rcp.approx.f32 %0, %1;" : "=f"(r) : "f"(x)); return r;
}
__device__ __forceinline__ ull pk2(float lo, float hi) {
    ull r; asm("mov.b64 %0, {%1,%2};" : "=l"(r) : "f"(lo), "f"(hi)); return r;
}
__device__ __forceinline__ void upk2(float& lo, float& hi, ull v) {
    asm("mov.b64 {%0,%1}, %2;" : "=f"(lo), "=f"(hi) : "l"(v));
}
__device__ __forceinline__ ull ffma2(ull a, ull b, ull c) {
    ull d; asm("fma.rn.f32x2 %0, %1, %2, %3;" : "=l"(d) : "l"(a), "l"(b), "l"(c)); return d;
}
__device__ __forceinline__ ull fmul2(ull a, ull b) {
    ull d; asm("mul.rn.f32x2 %0, %1, %2;" : "=l"(d) : "l"(a), "l"(b)); return d;
}
__device__ __forceinline__ ull fadd2(ull a, ull b) {
    ull d; asm("add.rn.f32x2 %0, %1, %2;" : "=l"(d) : "l"(a), "l"(b)); return d;
}

__global__ void __launch_bounds__(256, 1)
crf_forward(const float* __restrict__ em,
            const int* __restrict__ tags,
            const int* __restrict__ mask,
            const float* __restrict__ trans,
            float* __restrict__ out)
{
    __shared__ float tr_s[Kc * Kc];
    __shared__ __align__(16) float pbuf[WPB][2][Kc];  // double-buffered p
    __shared__ float red[WPB];
    __shared__ int   sdone;

    const int lane = threadIdx.x & 31;
    const int wid  = threadIdx.x >> 5;

    for (int i = threadIdx.x; i < Kc * Kc; i += 256)
        tr_s[i] = trans[i];
    __syncthreads();

    const float L2E = 1.4426950408889634f;   // log2(e)
    const float LN2 = 0.6931471805599453f;

    // lane j holds column j of E = exp(transitions), packed in state-pairs:
    // E2[k] = (E[2k], E[2k+1])
    ull E2[Kc / 2];
#pragma unroll
    for (int k = 0; k < Kc / 2; k++) {
        float elo = __expf(tr_s[(2 * k + 0) * Kc + lane]);
        float ehi = __expf(tr_s[(2 * k + 1) * Kc + lane]);
        E2[k] = pk2(elo, ehi);
    }

    const int b = blockIdx.x * WPB + wid;
    const float* emB = em   + (size_t)b * Tc * Kc;
    const int*   tgB = tags + (size_t)b * Tc;
    const int*   mB  = mask + (size_t)b * Tc;

    // ---- init: alpha0 = em[0]; p = 2^((em0-em0[0])*L2E); cacc(log2) ----
    float em0  = emB[lane];
    float r00  = __shfl_sync(FULLM, em0, 0);
    float cacc = r00 * L2E;
    float p    = ex2f_((em0 - r00) * L2E);    // p[0] == 1
    pbuf[wid][0][lane] = p;                    // seed buffer for t=1
    float p0seen = 1.0f;                       // tracked p[0]

    // prefetch ring: r_t = 2^(em*L2E) for rows t..t+3
    float nx0 = ex2f_(emB[0 * Kc + lane] * L2E);
    float nx1 = ex2f_(emB[1 * Kc + lane] * L2E);
    float nx2 = ex2f_(emB[2 * Kc + lane] * L2E);
    float nx3 = ex2f_(emB[3 * Kc + lane] * L2E);

    // chunk score pipeline: current chunk (c) + next chunk (n) prefetched
    int   tg_c = tgB[lane];
    int   mk_c = mB[lane];
    float et_c = emB[(size_t)lane * Kc + tg_c];
    int   tg_n = tgB[32 + lane];
    int   mk_n = mB[32 + lane];

    float escore = 0.f, tscore = 0.f;
    int   cry = 0;

    for (int ch = 0; ch < Tc / 32; ch++) {
        // ---- consume chunk ch's prefetched tag/mask/emtag ----
        unsigned mbits = __ballot_sync(FULLM, mk_c != 0);
        int tp = __shfl_up_sync(FULLM, tg_c, 1);
        if (lane == 0) tp = cry;
        cry = __shfl_sync(FULLM, tg_c, 31);
        const int t_l = ch * 32 + lane;
        if (mk_c) {
            escore += et_c;
            if (t_l > 0) tscore += tr_s[tp * Kc + tg_c];
        }
        // ---- prefetch: emtag gather for ch+1, tags/mask for ch+2 ----
        int chn  = min(ch + 1, Tc / 32 - 1);
        int chnn = min(ch + 2, Tc / 32 - 1);
        float et_n = emB[(size_t)(chn * 32 + lane) * Kc + tg_n];
        int tg_nn = tgB[chnn * 32 + lane];
        int mk_nn = mB[chnn * 32 + lane];

        for (int jj = 0; jj < 32; jj += 4) {
            const int tb = ch * 32 + jj;

            // renorm factor from p[0] (1-block-stale, all lanes agree)
            float rb = rcpf_(p0seen);
            float lb = lg2f_(rb);

            float rq[4] = {nx0, nx1, nx2, nx3};
            int t4 = min(tb + 4, Tc - 1);
            int t5 = min(tb + 5, Tc - 1);
            int t6 = min(tb + 6, Tc - 1);
            int t7 = min(tb + 7, Tc - 1);
            nx0 = ex2f_(emB[t4 * Kc + lane] * L2E);
            nx1 = ex2f_(emB[t5 * Kc + lane] * L2E);
            nx2 = ex2f_(emB[t6 * Kc + lane] * L2E);
            nx3 = ex2f_(emB[t7 * Kc + lane] * L2E);

#pragma unroll
            for (int q = 0; q < 4; q++) {
                const int t = tb + q;
                __syncwarp();                       // stores(t-1) -> loads(t)
                if (t != 0) {
                    const ulonglong2* pv = reinterpret_cast<const ulonglong2*>(
                        pbuf[wid][(t + 1) & 1]);    // buffer written at t-1

                    // 8x LDS.128 -> 16 packed pairs; pair k -> acc k%4
                    ulonglong2 y0 = pv[0], y1 = pv[1], y2 = pv[2], y3 = pv[3];
                    ulonglong2 y4 = pv[4], y5 = pv[5], y6 = pv[6], y7 = pv[7];

                    ull a0 = fmul2(y0.x, E2[0]);
                    ull a1 = fmul2(y0.y, E2[1]);
                    ull a2 = fmul2(y1.x, E2[2]);
                    ull a3 = fmul2(y1.y, E2[3]);
                    a0 = ffma2(y2.x, E2[4],  a0);
                    a1 = ffma2(y2.y, E2[5],  a1);
                    a2 = ffma2(y3.x, E2[6],  a2);
                    a3 = ffma2(y3.y, E2[7],  a3);
                    a0 = ffma2(y4.x, E2[8],  a0);
                    a1 = ffma2(y4.y, E2[9],  a1);
                    a2 = ffma2(y5.x, E2[10], a2);
                    a3 = ffma2(y5.y, E2[11], a3);
                    a0 = ffma2(y6.x, E2[12], a0);
                    a1 = ffma2(y6.y, E2[13], a1);
                    a2 = ffma2(y7.x, E2[14], a2);
                    a3 = ffma2(y7.y, E2[15], a3);

                    ull sp = fadd2(fadd2(a0, a1), fadd2(a2, a3));
                    float slo, shi;
                    upk2(slo, shi, sp);
                    float s = slo + shi;

                    // p[0] = lo half of first pair (free renorm sample)
                    float x00, x01;
                    upk2(x00, x01, y0.x);

                    float pn = s * rq[q];
                    bool  m  = (mbits >> (jj + q)) & 1u;
                    p = m ? pn : p;
                    if (q == 0) {                   // uniform renorm, post-sel
                        p    *= rb;
                        cacc -= lb;
                    }
                    p0seen = (q == 0) ? x00 * rb : x00;
                }
                pbuf[wid][t & 1][lane] = p;          // store p(t)
            }
        }

        // rotate chunk pipeline
        tg_c = tg_n; mk_c = mk_n; et_c = et_n;
        tg_n = tg_nn; mk_n = mk_nn;
    }

    // ---- final: logz = (cacc + lg2(sum_j p_j)) * ln2 ----
    float ps = p;
    float sc = escore + tscore;
#pragma unroll
    for (int o = 16; o; o >>= 1) {
        ps += __shfl_xor_sync(FULLM, ps, o);
        sc += __shfl_xor_sync(FULLM, sc, o);
    }
    float logz = (cacc + lg2f_(ps)) * LN2;

    if (lane == 0)
        __stcg(&g_partial[b], logz - sc);

    // ---- fused mean: last block to arrive reduces all partials ----
    __syncthreads();
    if (threadIdx.x == 0) {
        __threadfence();
        unsigned r = atomicInc(&g_ctr, (unsigned)gridDim.x - 1);
        sdone = (r == gridDim.x - 1) ? 1 : 0;
    }
    __syncthreads();
    if (sdone) {
        float s = 0.f;
        for (int i = threadIdx.x; i < Bc; i += 256)
            s += __ldcg(&g_partial[i]);
#pragma unroll
        for (int o = 16; o; o >>= 1)
            s += __shfl_xor_sync(FULLM, s, o);
        if (lane == 0) red[wid] = s;
        __syncthreads();
        if (threadIdx.x < 32) {
            float v = (threadIdx.x < WPB) ? red[threadIdx.x] : 0.f;
#pragma unroll
            for (int o = 4; o; o >>= 1)
                v += __shfl_xor_sync(FULLM, v, o);
            if (threadIdx.x == 0)
                out[0] = v * (1.0f / (float)Bc);
        }
    }
}

extern "C" void kernel_launch(void* const* d_in, const int* in_sizes, int n_in,
                              void* d_out, int out_size)
{
    const float* em    = (const float*)d_in[0];
    const int*   tags  = (const int*)d_in[1];
    const int*   mask  = (const int*)d_in[2];
    const float* trans = (const float*)d_in[3];
    float*       out   = (float*)d_out;

    crf_forward<<<NBLK, 256>>>(em, tags, mask, trans, out);
}